// round 7
// baseline (speedup 1.0000x reference)
#include <cuda_runtime.h>
#include <math.h>

#define N 1024
#define C 128
#define H 4
#define HD 32
#define HID 64
#define TI 32
#define TJ 64

typedef unsigned long long u64;

// ---- packed f32x2 helpers (sm_103a) ----
#define PACK2(d, lo, hi) asm("mov.b64 %0, {%1, %2};" : "=l"(d) : "f"(lo), "f"(hi))
#define UNPACK2(lo, hi, s) asm("mov.b64 {%0, %1}, %2;" : "=f"(lo), "=f"(hi) : "l"(s))
#define ADD2(d, a, b) asm("add.rn.f32x2 %0, %1, %2;" : "=l"(d) : "l"(a), "l"(b))
#define FMA2(d, a, b) asm("fma.rn.f32x2 %0, %1, %2, %0;" : "+l"(d) : "l"(a), "l"(b))

// ---- scratch (device globals) ----
__device__ float  g_q[N * C];
__device__ float  g_k[N * C];
__device__ float  g_v[N * C];
__device__ float4 g_A4[N * HID];     // [i][m] -> {A[i,h=0..3,m]}
__device__ float  g_qb2[N * H];
__device__ float  g_Pib[N * HID];    // pos[i]@W1 + b1
__device__ float  g_negPj[N * HID];  // -(pos[j]@W1)
__device__ float  g_scores[(size_t)H * N * N];

// ---------------------------------------------------------------
// K1 v3: qkv GEMM, latency-optimized. grid (N/8, 3), block 256.
// 8 rows per block; thread (c, rh): col c, rows rh..rh+3.
// x staged transposed so 4 rows load as one broadcast LDS.128.
// ---------------------------------------------------------------
__global__ void __launch_bounds__(256) qkv_kernel(
        const float* __restrict__ x, const float* __restrict__ y,
        const float* __restrict__ Wq, const float* __restrict__ bq,
        const float* __restrict__ Wk, const float* __restrict__ bk,
        const float* __restrict__ Wv, const float* __restrict__ bv) {
    int n0 = blockIdx.x * 8;
    int which = blockIdx.y;  // 0=q, 1=k, 2=v
    const float* in = (which == 0) ? x : y;
    const float* W  = (which == 0) ? Wq : (which == 1 ? Wk : Wv);
    const float* b  = (which == 0) ? bq : (which == 1 ? bk : bv);
    float* out      = (which == 0) ? g_q : (which == 1 ? g_k : g_v);

    __shared__ __align__(16) float xsT[C][12];  // [k][row], 48B stride

    int t = threadIdx.x;
    for (int idx = t; idx < 8 * C; idx += 256) {
        int r = idx >> 7, c = idx & 127;
        xsT[c][r] = in[(n0 + r) * C + c];
    }
    __syncthreads();

    int c  = t & 127;
    int rh = (t >> 7) * 4;  // 0 or 4
    float bc = b[c];
    float a0 = bc, a1 = bc, a2 = bc, a3 = bc;

#pragma unroll 8
    for (int k = 0; k < C; k++) {
        float w = W[k * C + c];
        float4 xv = *(const float4*)&xsT[k][rh];
        a0 += xv.x * w;
        a1 += xv.y * w;
        a2 += xv.z * w;
        a3 += xv.w * w;
    }
    out[(n0 + rh + 0) * C + c] = a0;
    out[(n0 + rh + 1) * C + c] = a1;
    out[(n0 + rh + 2) * C + c] = a2;
    out[(n0 + rh + 3) * C + c] = a3;
}

// ---------------------------------------------------------------
// K2: standalone coalesced prep (R5 version). grid N/16, block 256.
// ---------------------------------------------------------------
__global__ void __launch_bounds__(256) prep_kernel(
        const float* __restrict__ pos,
        const float* __restrict__ W1, const float* __restrict__ b1,
        const float* __restrict__ W2, const float* __restrict__ b2) {
    int i0 = blockIdx.x * 16;
    __shared__ float W2s[HID][C + 1];
    __shared__ float qs[16][C];
    __shared__ float b2s[C];

    int t = threadIdx.x;
    for (int idx = t; idx < HID * C; idx += 256)
        W2s[idx >> 7][idx & 127] = W2[idx];
    for (int idx = t; idx < 16 * C; idx += 256)
        qs[idx >> 7][idx & 127] = g_q[(i0 + (idx >> 7)) * C + (idx & 127)];
    if (t < C) b2s[t] = b2[t];
    __syncthreads();

    int m = t & 63;
    int isub = t >> 6;
    float w1x = W1[m], w1y = W1[HID + m], w1z = W1[2 * HID + m];
    float b1m = b1[m];

#pragma unroll
    for (int p = 0; p < 4; p++) {
        int il = p * 4 + isub;
        int i = i0 + il;
        const float* qrow = qs[il];

        float4 a = make_float4(0.f, 0.f, 0.f, 0.f);
#pragma unroll
        for (int d = 0; d < HD; d++) {
            a.x += W2s[m][0 * HD + d] * qrow[0 * HD + d];
            a.y += W2s[m][1 * HD + d] * qrow[1 * HD + d];
            a.z += W2s[m][2 * HD + d] * qrow[2 * HD + d];
            a.w += W2s[m][3 * HD + d] * qrow[3 * HD + d];
        }
        g_A4[i * HID + m] = a;

        float px = pos[i * 3 + 0], py = pos[i * 3 + 1], pz = pos[i * 3 + 2];
        float p1 = px * w1x + py * w1y + pz * w1z;
        g_negPj[i * HID + m] = -p1;
        g_Pib[i * HID + m]   = p1 + b1m;

        if (m < H) {
            float s = 0.f;
#pragma unroll
            for (int d = 0; d < HD; d++) s += qrow[m * HD + d] * b2s[m * HD + d];
            g_qb2[i * H + m] = s;
        }
    }
}

// ---------------------------------------------------------------
// K3: scores, packed f32x2 (unchanged from R6).
// ---------------------------------------------------------------
struct ScoresSmem {
    float  qs[TI][132];
    float  ksT[C][TJ + 2];
    float  Pib[TI][HID];
    float  nPjT[HID][TJ + 2];
    float4 A4[TI][HID + 2];
    float  pis[TI][3];
    float  pjs[TJ][3];
    float  qb2[TI][4];
};

__global__ void __launch_bounds__(256, 2) scores_kernel(const float* __restrict__ pos) {
    extern __shared__ __align__(16) char s_raw[];
    ScoresSmem& s = *reinterpret_cast<ScoresSmem*>(s_raw);

    int i0 = blockIdx.y * TI;
    int j0 = blockIdx.x * TJ;
    int tid = threadIdx.x;
    const float inv_sqrt_hd = 0.17677669529663687f;

    {
        const float4* gq4 = (const float4*)g_q;
        for (int t = tid; t < TI * 32; t += 256) {
            int r = t >> 5, c4 = t & 31;
            float4 v = gq4[(i0 + r) * 32 + c4];
            v.x *= inv_sqrt_hd; v.y *= inv_sqrt_hd; v.z *= inv_sqrt_hd; v.w *= inv_sqrt_hd;
            *(float4*)&s.qs[r][c4 * 4] = v;
        }
        const float4* gk4 = (const float4*)g_k;
        for (int t = tid; t < TJ * 32; t += 256) {
            int j = t >> 5, c4 = t & 31;
            float4 v = gk4[(j0 + j) * 32 + c4];
            s.ksT[c4 * 4 + 0][j] = v.x;
            s.ksT[c4 * 4 + 1][j] = v.y;
            s.ksT[c4 * 4 + 2][j] = v.z;
            s.ksT[c4 * 4 + 3][j] = v.w;
        }
        const float4* gp4 = (const float4*)g_negPj;
        for (int t = tid; t < TJ * 16; t += 256) {
            int j = t >> 4, m4 = t & 15;
            float4 v = gp4[(j0 + j) * 16 + m4];
            s.nPjT[m4 * 4 + 0][j] = v.x;
            s.nPjT[m4 * 4 + 1][j] = v.y;
            s.nPjT[m4 * 4 + 2][j] = v.z;
            s.nPjT[m4 * 4 + 3][j] = v.w;
        }
    }
    for (int t = tid; t < TI * HID; t += 256) {
        int r = t >> 6, m = t & 63;
        s.Pib[r][m] = g_Pib[(i0 + r) * HID + m];
        s.A4[r][m]  = g_A4[(i0 + r) * HID + m];
    }
    if (tid < TI) {
        s.pis[tid][0] = pos[(i0 + tid) * 3 + 0];
        s.pis[tid][1] = pos[(i0 + tid) * 3 + 1];
        s.pis[tid][2] = pos[(i0 + tid) * 3 + 2];
    }
    if (tid < TJ) {
        s.pjs[tid][0] = pos[(j0 + tid) * 3 + 0];
        s.pjs[tid][1] = pos[(j0 + tid) * 3 + 1];
        s.pjs[tid][2] = pos[(j0 + tid) * 3 + 2];
    }
    if (tid < TI * H) {
        s.qb2[tid >> 2][tid & 3] = g_qb2[(i0 + (tid >> 2)) * H + (tid & 3)];
    }
    __syncthreads();

    int il = tid >> 4;
    int jt = tid & 15;
    int ia = il, ib = il + 16;
    int jc0 = 2 * jt;
    int jc1 = 2 * jt + 32;

    u64 acc[2][4][2];
#pragma unroll
    for (int h = 0; h < 4; h++) {
        float qa = s.qb2[ia][h], qb = s.qb2[ib][h];
        u64 ta, tb;
        PACK2(ta, qa, qa); PACK2(tb, qb, qb);
        acc[0][h][0] = ta; acc[0][h][1] = ta;
        acc[1][h][0] = tb; acc[1][h][1] = tb;
    }

#pragma unroll 4
    for (int m = 0; m < HID; m++) {
        float pa = s.Pib[ia][m], pb = s.Pib[ib][m];
        u64 pa2, pb2;
        PACK2(pa2, pa, pa); PACK2(pb2, pb, pb);
        u64 n0 = *(const u64*)&s.nPjT[m][jc0];
        u64 n1 = *(const u64*)&s.nPjT[m][jc1];

        u64 za0, za1, zb0, zb1;
        ADD2(za0, pa2, n0); ADD2(za1, pa2, n1);
        ADD2(zb0, pb2, n0); ADD2(zb1, pb2, n1);

        float lo, hi;
        u64 ha0, ha1, hb0, hb1;
        UNPACK2(lo, hi, za0); PACK2(ha0, fmaxf(lo, 0.f), fmaxf(hi, 0.f));
        UNPACK2(lo, hi, za1); PACK2(ha1, fmaxf(lo, 0.f), fmaxf(hi, 0.f));
        UNPACK2(lo, hi, zb0); PACK2(hb0, fmaxf(lo, 0.f), fmaxf(hi, 0.f));
        UNPACK2(lo, hi, zb1); PACK2(hb1, fmaxf(lo, 0.f), fmaxf(hi, 0.f));

        float4 aa = s.A4[ia][m], ab = s.A4[ib][m];
        u64 ax, ay, az, aw, bx, by, bz, bw;
        PACK2(ax, aa.x, aa.x); PACK2(ay, aa.y, aa.y);
        PACK2(az, aa.z, aa.z); PACK2(aw, aa.w, aa.w);
        PACK2(bx, ab.x, ab.x); PACK2(by, ab.y, ab.y);
        PACK2(bz, ab.z, ab.z); PACK2(bw, ab.w, ab.w);

        FMA2(acc[0][0][0], ha0, ax); FMA2(acc[0][0][1], ha1, ax);
        FMA2(acc[0][1][0], ha0, ay); FMA2(acc[0][1][1], ha1, ay);
        FMA2(acc[0][2][0], ha0, az); FMA2(acc[0][2][1], ha1, az);
        FMA2(acc[0][3][0], ha0, aw); FMA2(acc[0][3][1], ha1, aw);
        FMA2(acc[1][0][0], hb0, bx); FMA2(acc[1][0][1], hb1, bx);
        FMA2(acc[1][1][0], hb0, by); FMA2(acc[1][1][1], hb1, by);
        FMA2(acc[1][2][0], hb0, bz); FMA2(acc[1][2][1], hb1, bz);
        FMA2(acc[1][3][0], hb0, bw); FMA2(acc[1][3][1], hb1, bw);
    }

#pragma unroll
    for (int h = 0; h < 4; h++) {
#pragma unroll
        for (int d2 = 0; d2 < 16; d2++) {
            int c = h * HD + 2 * d2;
            float2 qa = *(const float2*)&s.qs[ia][c];
            float2 qb = *(const float2*)&s.qs[ib][c];
            u64 k00 = *(const u64*)&s.ksT[c][jc0];
            u64 k01 = *(const u64*)&s.ksT[c][jc1];
            u64 k10 = *(const u64*)&s.ksT[c + 1][jc0];
            u64 k11 = *(const u64*)&s.ksT[c + 1][jc1];
            u64 qa0, qa1, qb0, qb1;
            PACK2(qa0, qa.x, qa.x); PACK2(qa1, qa.y, qa.y);
            PACK2(qb0, qb.x, qb.x); PACK2(qb1, qb.y, qb.y);
            FMA2(acc[0][h][0], qa0, k00); FMA2(acc[0][h][1], qa0, k01);
            FMA2(acc[0][h][0], qa1, k10); FMA2(acc[0][h][1], qa1, k11);
            FMA2(acc[1][h][0], qb0, k00); FMA2(acc[1][h][1], qb0, k01);
            FMA2(acc[1][h][0], qb1, k10); FMA2(acc[1][h][1], qb1, k11);
        }
    }

    float pax = s.pis[ia][0], pay = s.pis[ia][1], paz = s.pis[ia][2];
    float pbx = s.pis[ib][0], pby = s.pis[ib][1], pbz = s.pis[ib][2];
    float da[2][2], db[2][2];
#pragma unroll
    for (int p = 0; p < 2; p++) {
        int jc = (p == 0) ? jc0 : jc1;
#pragma unroll
        for (int e = 0; e < 2; e++) {
            int j = jc + e;
            float jx = s.pjs[j][0], jy = s.pjs[j][1], jz = s.pjs[j][2];
            float x0 = pax - jx, y0_ = pay - jy, z0 = paz - jz;
            float x1 = pbx - jx, y1_ = pby - jy, z1 = pbz - jz;
            da[p][e] = sqrtf(x0 * x0 + y0_ * y0_ + z0 * z0);
            db[p][e] = sqrtf(x1 * x1 + y1_ * y1_ + z1 * z1);
        }
    }

    int iga = i0 + ia, igb = i0 + ib;
#pragma unroll
    for (int h = 0; h < 4; h++) {
        size_t basea = ((size_t)h * N + iga) * N + j0;
        size_t baseb = ((size_t)h * N + igb) * N + j0;
#pragma unroll
        for (int p = 0; p < 2; p++) {
            int jc = (p == 0) ? jc0 : jc1;
            float lo, hi;
            UNPACK2(lo, hi, acc[0][h][p]);
            float2 sca = make_float2(lo - da[p][0], hi - da[p][1]);
            UNPACK2(lo, hi, acc[1][h][p]);
            float2 scb = make_float2(lo - db[p][0], hi - db[p][1]);
            *(float2*)&g_scores[basea + jc] = sca;
            *(float2*)&g_scores[baseb + jc] = scb;
        }
    }
}

// ---------------------------------------------------------------
// K4: softmax + PV (unchanged from R6). grid (N/8, H), block 128.
// ---------------------------------------------------------------
struct SoftmaxSmem {
    float es[8][1032];
    float red[4][8][33];
    float inv_sum[8];
};

__global__ void __launch_bounds__(128) softmax_out_kernel(float* __restrict__ out) {
    extern __shared__ __align__(16) char s_raw[];
    SoftmaxSmem& s = *reinterpret_cast<SoftmaxSmem*>(s_raw);

    int h = blockIdx.y;
    int i0 = blockIdx.x * 8;
    int warp = threadIdx.x >> 5, lane = threadIdx.x & 31;

#pragma unroll
    for (int rr = 0; rr < 2; rr++) {
        int r = warp + rr * 4;
        int i = i0 + r;
        const float4* srow = (const float4*)(g_scores + ((size_t)h * N + i) * N);

        float4 xv[8];
        float m = -INFINITY;
#pragma unroll
        for (int t = 0; t < 8; t++) {
            xv[t] = srow[t * 32 + lane];
            m = fmaxf(m, fmaxf(fmaxf(xv[t].x, xv[t].y), fmaxf(xv[t].z, xv[t].w)));
        }
#pragma unroll
        for (int o = 16; o; o >>= 1) m = fmaxf(m, __shfl_xor_sync(0xFFFFFFFFu, m, o));

        float sum = 0.f;
#pragma unroll
        for (int t = 0; t < 8; t++) {
            float4 e;
            e.x = __expf(xv[t].x - m);
            e.y = __expf(xv[t].y - m);
            e.z = __expf(xv[t].z - m);
            e.w = __expf(xv[t].w - m);
            *(float4*)&s.es[r][t * 128 + lane * 4] = e;
            sum += (e.x + e.y) + (e.z + e.w);
        }
#pragma unroll
        for (int o = 16; o; o >>= 1) sum += __shfl_xor_sync(0xFFFFFFFFu, sum, o);
        if (lane == 0) s.inv_sum[r] = 1.0f / sum;
    }
    __syncthreads();

    u64 acc[8];
    {
        u64 z; PACK2(z, 0.f, 0.f);
#pragma unroll
        for (int r = 0; r < 8; r++) acc[r] = z;
    }

    const float* vb = g_v + h * HD + lane;
    int jbase = warp * 256;
#pragma unroll 2
    for (int j = jbase; j < jbase + 256; j += 4) {
        float v0 = vb[(j + 0) * C];
        float v1 = vb[(j + 1) * C];
        float v2 = vb[(j + 2) * C];
        float v3 = vb[(j + 3) * C];
        u64 v01, v23;
        PACK2(v01, v0, v1); PACK2(v23, v2, v3);
#pragma unroll
        for (int r = 0; r < 8; r++) {
            float4 e4 = *(const float4*)&s.es[r][j];
            u64 e01, e23;
            PACK2(e01, e4.x, e4.y); PACK2(e23, e4.z, e4.w);
            FMA2(acc[r], e01, v01);
            FMA2(acc[r], e23, v23);
        }
    }
#pragma unroll
    for (int r = 0; r < 8; r++) {
        float lo, hi;
        UNPACK2(lo, hi, acc[r]);
        s.red[warp][r][lane] = lo + hi;
    }
    __syncthreads();

#pragma unroll
    for (int o = threadIdx.x; o < 256; o += 128) {
        int r = o >> 5, d = o & 31;
        float v = (s.red[0][r][d] + s.red[1][r][d]) + (s.red[2][r][d] + s.red[3][r][d]);
        out[(i0 + r) * C + h * HD + d] = v * s.inv_sum[r];
    }
}

// ---------------------------------------------------------------
extern "C" void kernel_launch(void* const* d_in, const int* in_sizes, int n_in,
                              void* d_out, int out_size) {
    (void)in_sizes; (void)n_in; (void)out_size;
    const float* x   = (const float*)d_in[0];
    const float* y   = (const float*)d_in[1];
    const float* pos = (const float*)d_in[2];
    const float* Wq  = (const float*)d_in[3];
    const float* bq  = (const float*)d_in[4];
    const float* Wk  = (const float*)d_in[5];
    const float* bk  = (const float*)d_in[6];
    const float* Wv  = (const float*)d_in[7];
    const float* bv  = (const float*)d_in[8];
    const float* W1  = (const float*)d_in[9];
    const float* b1  = (const float*)d_in[10];
    const float* W2  = (const float*)d_in[11];
    const float* b2  = (const float*)d_in[12];
    float* out = (float*)d_out;

    static bool attrs_set = false;
    if (!attrs_set) {
        cudaFuncSetAttribute(scores_kernel, cudaFuncAttributeMaxDynamicSharedMemorySize,
                             (int)sizeof(ScoresSmem));
        cudaFuncSetAttribute(softmax_out_kernel, cudaFuncAttributeMaxDynamicSharedMemorySize,
                             (int)sizeof(SoftmaxSmem));
        attrs_set = true;
    }

    qkv_kernel<<<dim3(N / 8, 3), 256>>>(x, y, Wq, bq, Wk, bk, Wv, bv);
    prep_kernel<<<N / 16, 256>>>(pos, W1, b1, W2, b2);
    scores_kernel<<<dim3(N / TJ, N / TI), 256, sizeof(ScoresSmem)>>>(pos);
    softmax_out_kernel<<<dim3(N / 8, H), 128, sizeof(SoftmaxSmem)>>>(out);
}